// round 14
// baseline (speedup 1.0000x reference)
#include <cuda_runtime.h>
#include <cuda_fp16.h>
#include <math.h>
#include <stdint.h>

// Problem constants (fixed by this dataset instance)
#define Bsz 2
#define Sq  2048
#define Dm  1024
#define Hn  16
#define Dk  64
#define Mrows (Bsz*Sq)   // 4096

// ---------------- scratch ----------------------------------------------------
__device__ __half g_xhi[Mrows*Dm];                     // x: fp16 hi only
__device__ __half g_wqhi[Dm*Dm];                       // weights: fp16 hi only
__device__ __half g_wkhi[Dm*Dm];
__device__ __half g_wvhi[Dm*Dm];
__device__ __half g_wohi[Dm*Dm];
__device__ __half g_Qhi[Mrows*Dm];                     // [B,H,S,Dk] fp16 hi
__device__ __half g_Khi[Mrows*Dm];
__device__ __half g_Vhi[Mrows*Dm];
__device__ __half g_Ohi[Mrows*Dm];                     // [B,S,D] fp16 hi
__device__ float2 g_rope[Mrows*(Dk/2)];                // [row, dk/2] = {cos, sin}

// ================= small PTX wrappers (portable, compute_103-safe) ===========
__device__ __forceinline__ uint32_t smem_u32(const void* p) {
    uint32_t a;
    asm("{ .reg .u64 t; cvta.to.shared.u64 t, %1; cvt.u32.u64 %0, t; }"
        : "=r"(a) : "l"(p));
    return a;
}
__device__ __forceinline__ void ldsm_x4(uint32_t addr, uint32_t r[4]) {
    asm volatile("ldmatrix.sync.aligned.m8n8.x4.shared.b16 {%0,%1,%2,%3}, [%4];"
                 : "=r"(r[0]), "=r"(r[1]), "=r"(r[2]), "=r"(r[3]) : "r"(addr));
}
__device__ __forceinline__ void ldsm_x2(uint32_t addr, uint32_t r[2]) {
    asm volatile("ldmatrix.sync.aligned.m8n8.x2.shared.b16 {%0,%1}, [%2];"
                 : "=r"(r[0]), "=r"(r[1]) : "r"(addr));
}
__device__ __forceinline__ void ldsm_x2t(uint32_t addr, uint32_t r[2]) {
    asm volatile("ldmatrix.sync.aligned.m8n8.x2.trans.shared.b16 {%0,%1}, [%2];"
                 : "=r"(r[0]), "=r"(r[1]) : "r"(addr));
}
__device__ __forceinline__ void mma_f16(float c[4], const uint32_t a[4],
                                        const uint32_t b[2]) {
    asm volatile(
        "mma.sync.aligned.m16n8k16.row.col.f32.f16.f16.f32 "
        "{%0,%1,%2,%3}, {%4,%5,%6,%7}, {%8,%9}, {%0,%1,%2,%3};"
        : "+f"(c[0]), "+f"(c[1]), "+f"(c[2]), "+f"(c[3])
        : "r"(a[0]), "r"(a[1]), "r"(a[2]), "r"(a[3]), "r"(b[0]), "r"(b[1]));
}
__device__ __forceinline__ void cp16(uint32_t smem_addr, const void* gptr) {
    asm volatile("cp.async.cg.shared.global [%0], [%1], 16;"
                 :: "r"(smem_addr), "l"(gptr) : "memory");
}
#define CP_COMMIT() asm volatile("cp.async.commit_group;" ::: "memory")
#define CP_WAIT(n)  asm volatile("cp.async.wait_group %0;" :: "n"(n) : "memory")

__device__ __forceinline__ uint32_t pack_hf2(float x, float y) {
    __half2 t = __floats2half2_rn(x, y);
    return *reinterpret_cast<uint32_t*>(&t);
}

// ================= fused split pass + RoPE table ==============================
#define NX4 (Mrows*Dm/4)    // 1048576
#define NW4 (Dm*Dm/4)       // 262144
#define NTOT4 (NX4 + 4*NW4) // 2097152
#define SPLIT_STRIDE (NTOT4/4)          // 524288 threads
#define SPLIT_CTAS (SPLIT_STRIDE/256)   // 2048
#define ROPE_N (Mrows*(Dk/2))           // 131072
#define ROPE_CTAS (ROPE_N/256)          // 512

__global__ void __launch_bounds__(256)
split_all_kernel(const float* __restrict__ x,  const float* __restrict__ Wq,
                 const float* __restrict__ Wk, const float* __restrict__ Wv,
                 const float* __restrict__ Wo, const int* __restrict__ pos,
                 __half* __restrict__ xhi,
                 __half* __restrict__ wqhi, __half* __restrict__ wkhi,
                 __half* __restrict__ wvhi, __half* __restrict__ wohi,
                 float2* __restrict__ ropeTab)
{
    const int bid = blockIdx.x;
    if (bid < SPLIT_CTAS) {
        #pragma unroll
        for (int k = 0; k < 4; k++) {
            int i = bid * 256 + threadIdx.x + k * SPLIT_STRIDE;
            const float* src; __half* hi; int j;
            if (i < NX4) { src = x; hi = xhi; j = i; }
            else {
                int t = (i - NX4) >> 18;            // which weight (NW4 = 2^18)
                j = (i - NX4) & (NW4 - 1);
                if      (t == 0) { src = Wq; hi = wqhi; }
                else if (t == 1) { src = Wk; hi = wkhi; }
                else if (t == 2) { src = Wv; hi = wvhi; }
                else             { src = Wo; hi = wohi; }
            }
            float4 v = reinterpret_cast<const float4*>(src)[j];
            reinterpret_cast<uint2*>(hi)[j] =
                make_uint2(pack_hf2(v.x, v.y), pack_hf2(v.z, v.w));
        }
    } else {
        const int gid = (bid - SPLIT_CTAS) * 256 + threadIdx.x;   // 0..131071
        const int m   = gid >> 5;
        const int dkh = gid & 31;
        const float p = (float)pos[m];
        const float inv = exp2f((float)(2 * dkh) * (-13.287712379549449f / 64.0f));
        float sn, cs;
        sincosf(p * inv, &sn, &cs);
        ropeTab[gid] = make_float2(cs, sn);
    }
}

// ================= shared GEMM machinery (single-term fp16) ===================
#define BM 128
#define BN 128
#define BK 32
#define KT_ITERS (Dm/BK)              // 32
#define TPITCH 80
#define TILE_BYTES (128*TPITCH)        // 10240
#define STAGE_BYTES (2*TILE_BYTES)     // Ahi|Bhi = 20480
#define NSTAGE 4
#define GEMM_SMEM (NSTAGE*STAGE_BYTES) // 81920  (2 CTAs/SM)

struct GemmCore {
    uint32_t sbase;
    int lane, warp_m, warp_n, m0, n0;
    const __half *Ahi, *Bhi;
    int r0a, c0, r1a;

    __device__ __forceinline__ void issue_stage(int stage, int kt) {
        const int kc = kt * BK;
        const uint32_t sb = sbase + stage * STAGE_BYTES;
        cp16(sb + (uint32_t)(r0a * TPITCH + c0 * 16),
             Ahi + (size_t)(m0 + r0a) * Dm + kc + c0 * 8);
        cp16(sb + (uint32_t)(r1a * TPITCH + c0 * 16),
             Ahi + (size_t)(m0 + r1a) * Dm + kc + c0 * 8);
        cp16(sb + TILE_BYTES + (uint32_t)(r0a * TPITCH + c0 * 16),
             Bhi + (size_t)(n0 + r0a) * Dm + kc + c0 * 8);
        cp16(sb + TILE_BYTES + (uint32_t)(r1a * TPITCH + c0 * 16),
             Bhi + (size_t)(n0 + r1a) * Dm + kc + c0 * 8);
        CP_COMMIT();
    }

    __device__ __forceinline__ void mainloop(float acc[4][4][4]) {
        issue_stage(0, 0);
        issue_stage(1, 1);
        issue_stage(2, 2);
        for (int kt = 0; kt < KT_ITERS; kt++) {
            if (kt + 2 < KT_ITERS)      { CP_WAIT(2); }
            else if (kt + 1 < KT_ITERS) { CP_WAIT(1); }
            else                        { CP_WAIT(0); }
            __syncthreads();
            if (kt + 3 < KT_ITERS) issue_stage((kt + 3) & 3, kt + 3);

            const uint32_t sb = sbase + (kt & 3) * STAGE_BYTES;
            const uint32_t sAhi = sb;
            const uint32_t sBhi = sb + TILE_BYTES;

            #pragma unroll
            for (int ks = 0; ks < 2; ks++) {
                const int chunk = ks * 2;
                uint32_t bhi[4][2];
                #pragma unroll
                for (int nt = 0; nt < 4; nt++) {      // direct x2 loads
                    const int brow = warp_n * 32 + nt * 8 + (lane & 7);
                    const uint32_t boff = (uint32_t)(brow * TPITCH + (chunk + ((lane >> 3) & 1)) * 16);
                    ldsm_x2(sBhi + boff, bhi[nt]);
                }
                #pragma unroll
                for (int mt = 0; mt < 4; mt++) {
                    uint32_t ahi[4];
                    const int arow = warp_m * 64 + mt * 16 + (lane & 15);
                    const uint32_t aoff = (uint32_t)(arow * TPITCH + (chunk + (lane >> 4)) * 16);
                    ldsm_x4(sAhi + aoff, ahi);
                    #pragma unroll
                    for (int nt = 0; nt < 4; nt++)
                        mma_f16(acc[mt][nt], ahi, bhi[nt]);
                }
            }
        }
    }
};

// ---- persistent fused QKV GEMM: 296 CTAs loop over all 768 output tiles ------
#define QKV_TILES (3 * (Dm/BN) * (Mrows/BM))   // 768
#define QKV_GRID  296                           // 148 SMs x 2 CTAs

__global__ void __launch_bounds__(256, 2)
qkv_gemm_kernel(const __half* __restrict__ xhi,
                const __half* __restrict__ wqhi, const __half* __restrict__ wkhi,
                const __half* __restrict__ wvhi,
                __half* __restrict__ qhi, __half* __restrict__ khi,
                __half* __restrict__ vhi, const float2* __restrict__ ropeTab)
{
    extern __shared__ char sm[];
    const int tid = threadIdx.x;

    GemmCore gc;
    gc.sbase = smem_u32(sm);
    gc.lane = tid & 31;
    gc.warp_m = (tid >> 5) & 1; gc.warp_n = tid >> 6;
    gc.Ahi = xhi;
    gc.r0a = tid >> 2; gc.c0 = tid & 3; gc.r1a = (tid + 256) >> 2;

    for (int tile = blockIdx.x; tile < QKV_TILES; tile += QKV_GRID) {
        const int wsel = tile >> 8;             // 256 tiles per weight
        const int rem  = tile & 255;
        gc.n0 = (rem >> 5) * BN;
        gc.m0 = (rem & 31) * BM;

        __half* Chi;
        bool rope;
        if (wsel == 0)      { gc.Bhi = wqhi; Chi = qhi; rope = true;  }
        else if (wsel == 1) { gc.Bhi = wkhi; Chi = khi; rope = true;  }
        else                { gc.Bhi = wvhi; Chi = vhi; rope = false; }

        float acc[4][4][4];
        #pragma unroll
        for (int i = 0; i < 4; i++)
            #pragma unroll
            for (int j = 0; j < 4; j++)
                #pragma unroll
                for (int v = 0; v < 4; v++) acc[i][j][v] = 0.f;

        gc.mainloop(acc);

        // epilogue: fused RoPE (table lookup) + fp16 hi store to [B,H,S,Dk]
        const int lane = gc.lane;
        #pragma unroll
        for (int mt = 0; mt < 4; mt++) {
            #pragma unroll
            for (int half = 0; half < 2; half++) {
                const int row = gc.m0 + gc.warp_m * 64 + mt * 16 + (lane >> 2) + half * 8;
                const int b = row >> 11;
                const int s = row & (Sq - 1);
                #pragma unroll
                for (int nt = 0; nt < 4; nt++) {
                    const int col = gc.n0 + gc.warp_n * 32 + nt * 8 + (lane & 3) * 2;  // even
                    float e = acc[mt][nt][half * 2];
                    float o = acc[mt][nt][half * 2 + 1];
                    if (rope) {
                        const int dkh = (col & (Dk - 1)) >> 1;
                        const float2 cssn = ropeTab[row * (Dk / 2) + dkh];
                        const float re = e * cssn.x - o * cssn.y;
                        const float ro = e * cssn.y + o * cssn.x;
                        e = re; o = ro;
                    }
                    const int h  = col >> 6;
                    const int dk = col & (Dk - 1);
                    const size_t idx = ((size_t)(b * Hn + h) * Sq + s) * Dk + dk;
                    *reinterpret_cast<uint32_t*>(Chi + idx) = pack_hf2(e, o);
                }
            }
        }
        // Inter-tile smem safety: next mainloop's first consume waits on this
        // thread's own cp.async groups and the kt=0 __syncthreads; stage 0 was
        // last read 3 syncs before loop exit, so prologue writes cannot race.
    }
}

// ---- output projection GEMM: single-term, fp32 out (256 CTAs = 1 wave) -------
__global__ void __launch_bounds__(256, 2)
wo_gemm_kernel(const __half* __restrict__ Ahi, const __half* __restrict__ Bhi,
               float* __restrict__ C)
{
    extern __shared__ char sm[];
    const int tid = threadIdx.x;

    GemmCore gc;
    gc.sbase = smem_u32(sm);
    gc.lane = tid & 31;
    gc.warp_m = (tid >> 5) & 1; gc.warp_n = tid >> 6;
    gc.n0 = blockIdx.x * BN;
    gc.m0 = blockIdx.y * BM;
    gc.Ahi = Ahi; gc.Bhi = Bhi;
    gc.r0a = tid >> 2; gc.c0 = tid & 3; gc.r1a = (tid + 256) >> 2;

    float acc[4][4][4];
    #pragma unroll
    for (int i = 0; i < 4; i++)
        #pragma unroll
        for (int j = 0; j < 4; j++)
            #pragma unroll
            for (int v = 0; v < 4; v++) acc[i][j][v] = 0.f;

    gc.mainloop(acc);

    const int lane = gc.lane;
    #pragma unroll
    for (int mt = 0; mt < 4; mt++) {
        #pragma unroll
        for (int half = 0; half < 2; half++) {
            const int row = gc.m0 + gc.warp_m * 64 + mt * 16 + (lane >> 2) + half * 8;
            #pragma unroll
            for (int nt = 0; nt < 4; nt++) {
                const int col = gc.n0 + gc.warp_n * 32 + nt * 8 + (lane & 3) * 2;
                float* dst = C + (size_t)row * Dm + col;
                *reinterpret_cast<float2*>(dst) =
                    make_float2(acc[mt][nt][half * 2], acc[mt][nt][half * 2 + 1]);
            }
        }
    }
}

// ================= tensor-core causal flash attention (pure fp16) =============
#define ATPITCH 144
#define AT_TILE (64*ATPITCH)          // 9216
#define AT_STAGE (2*AT_TILE)          // Khi|Vhi = 18432
#define AT_NSTAGE 3
#define ATT_SMEM (AT_NSTAGE*AT_STAGE) // 55296  (2 CTAs/SM)

__global__ void __launch_bounds__(256, 2)
attn_mma_kernel(const __half* __restrict__ Qhi,
                const __half* __restrict__ Khi, const __half* __restrict__ Vhi,
                __half* __restrict__ Ohi)
{
    extern __shared__ char sm[];
    const uint32_t sbase = smem_u32(sm);

    const int tid  = threadIdx.x;
    const int lane = tid & 31;
    const int w    = tid >> 5;
    const int bh   = blockIdx.y;
    const int qt   = (int)gridDim.x - 1 - (int)blockIdx.x;   // big tiles first
    const int q0   = qt * 128;
    const int NT   = 2 * qt + 2;                             // key tiles (64 each)

    const size_t kvbase = (size_t)bh * Sq;

    // --- Q fragments (direct gmem gather, once) ------------------------------
    const int r  = q0 + w * 16 + (lane >> 2);
    const int dc = 2 * (lane & 3);
    uint32_t qh[4][4];
    #pragma unroll
    for (int c = 0; c < 4; c++) {
        const int d = c * 16 + dc;
        const size_t i00 = (kvbase + r) * Dk + d;
        const size_t i10 = (kvbase + r + 8) * Dk + d;
        qh[c][0] = *reinterpret_cast<const uint32_t*>(Qhi + i00);
        qh[c][1] = *reinterpret_cast<const uint32_t*>(Qhi + i10);
        qh[c][2] = *reinterpret_cast<const uint32_t*>(Qhi + i00 + 8);
        qh[c][3] = *reinterpret_cast<const uint32_t*>(Qhi + i10 + 8);
    }

    const __half* gkv[2] = {Khi, Vhi};
    auto issue_kv = [&](int stage, int it) {
        const int k0 = it * 64;
        const uint32_t sb = sbase + stage * AT_STAGE;
        #pragma unroll
        for (int i = 0; i < 4; i++) {
            const int c = tid + i * 256;          // 0..1023
            const int t = c >> 9;                 // tile 0..1
            const int rr = (c >> 3) & 63;         // row 0..63
            const int cl = c & 7;                 // 16B chunk 0..7
            cp16(sb + t * AT_TILE + (uint32_t)(rr * ATPITCH + cl * 16),
                 gkv[t] + (kvbase + k0 + rr) * Dk + cl * 8);
        }
        CP_COMMIT();
    };

    float o[8][4];
    #pragma unroll
    for (int nt = 0; nt < 8; nt++)
        #pragma unroll
        for (int j = 0; j < 4; j++) o[nt][j] = 0.f;
    float m0 = -1e30f, m1 = -1e30f, l0 = 0.f, l1 = 0.f;

    issue_kv(0, 0);
    issue_kv(1, 1);

    const float SCL = 0.125f * 1.4426950408889634f;  // scale * log2(e)

    for (int it = 0; it < NT; it++) {
        if (it + 1 < NT) { CP_WAIT(1); } else { CP_WAIT(0); }
        __syncthreads();
        if (it + 2 < NT) issue_kv((it + 2) % AT_NSTAGE, it + 2);  // single-sync pipeline

        const uint32_t sb  = sbase + (it % AT_NSTAGE) * AT_STAGE;
        const uint32_t sKh = sb;
        const uint32_t sVh = sb + AT_TILE;
        const int k0 = it * 64;

        // ---- S = Q K^T -------------------------------------------------------
        float s[8][4];
        #pragma unroll
        for (int nt = 0; nt < 8; nt++)
            #pragma unroll
            for (int j = 0; j < 4; j++) s[nt][j] = 0.f;

        #pragma unroll
        for (int c = 0; c < 4; c++) {
            #pragma unroll
            for (int nt = 0; nt < 8; nt++) {
                const uint32_t boff =
                    (uint32_t)((nt * 8 + (lane & 7)) * ATPITCH + c * 32 + ((lane >> 3) & 1) * 16);
                uint32_t kh[2];
                ldsm_x2(sKh + boff, kh);
                mma_f16(s[nt], qh[c], kh);
            }
        }

        // ---- online softmax (exp2 domain) ------------------------------------
        const bool need_mask = (k0 + 63 > q0);
        float t0 = -1e30f, t1 = -1e30f;
        #pragma unroll
        for (int nt = 0; nt < 8; nt++) {
            #pragma unroll
            for (int j = 0; j < 4; j++) {
                float t = s[nt][j] * SCL;
                if (need_mask) {
                    const int col = k0 + nt * 8 + dc + (j & 1);
                    const int row = (j < 2) ? r : r + 8;
                    if (col > row) t = -1e30f;
                }
                s[nt][j] = t;
                if (j < 2) t0 = fmaxf(t0, t); else t1 = fmaxf(t1, t);
            }
        }
        t0 = fmaxf(t0, __shfl_xor_sync(0xffffffffu, t0, 1));
        t0 = fmaxf(t0, __shfl_xor_sync(0xffffffffu, t0, 2));
        t1 = fmaxf(t1, __shfl_xor_sync(0xffffffffu, t1, 1));
        t1 = fmaxf(t1, __shfl_xor_sync(0xffffffffu, t1, 2));
        const float mn0 = fmaxf(m0, t0), mn1 = fmaxf(m1, t1);
        const float corr0 = exp2f(m0 - mn0), corr1 = exp2f(m1 - mn1);
        m0 = mn0; m1 = mn1;

        float ps0 = 0.f, ps1 = 0.f;
        #pragma unroll
        for (int nt = 0; nt < 8; nt++) {
            s[nt][0] = exp2f(s[nt][0] - m0);
            s[nt][1] = exp2f(s[nt][1] - m0);
            s[nt][2] = exp2f(s[nt][2] - m1);
            s[nt][3] = exp2f(s[nt][3] - m1);
            ps0 += s[nt][0] + s[nt][1];
            ps1 += s[nt][2] + s[nt][3];
        }
        ps0 += __shfl_xor_sync(0xffffffffu, ps0, 1);
        ps0 += __shfl_xor_sync(0xffffffffu, ps0, 2);
        ps1 += __shfl_xor_sync(0xffffffffu, ps1, 1);
        ps1 += __shfl_xor_sync(0xffffffffu, ps1, 2);
        l0 = l0 * corr0 + ps0;
        l1 = l1 * corr1 + ps1;

        #pragma unroll
        for (int nt = 0; nt < 8; nt++) {
            o[nt][0] *= corr0; o[nt][1] *= corr0;
            o[nt][2] *= corr1; o[nt][3] *= corr1;
        }

        // ---- O += P V ----------------------------------------------------------
        #pragma unroll
        for (int u = 0; u < 4; u++) {
            uint32_t aph[4];
            aph[0] = pack_hf2(s[2*u][0],   s[2*u][1]);
            aph[1] = pack_hf2(s[2*u][2],   s[2*u][3]);
            aph[2] = pack_hf2(s[2*u+1][0], s[2*u+1][1]);
            aph[3] = pack_hf2(s[2*u+1][2], s[2*u+1][3]);
            #pragma unroll
            for (int nt = 0; nt < 8; nt++) {
                const uint32_t voff =
                    (uint32_t)((u * 16 + (lane & 15)) * ATPITCH + nt * 16);
                uint32_t vh[2];
                ldsm_x2t(sVh + voff, vh);
                mma_f16(o[nt], aph, vh);
            }
        }
    }

    // ---- epilogue: normalize, fp16 hi store, write [B,S,D] -------------------
    const float inv0 = 1.0f / l0, inv1 = 1.0f / l1;
    const int b = bh >> 4, h = bh & 15;
    const size_t base0 = ((size_t)b * Sq + r) * Dm + h * Dk;
    const size_t base1 = ((size_t)b * Sq + r + 8) * Dm + h * Dk;
    #pragma unroll
    for (int nt = 0; nt < 8; nt++) {
        const int col = nt * 8 + dc;
        *reinterpret_cast<uint32_t*>(Ohi + base0 + col) =
            pack_hf2(o[nt][0] * inv0, o[nt][1] * inv0);
        *reinterpret_cast<uint32_t*>(Ohi + base1 + col) =
            pack_hf2(o[nt][2] * inv1, o[nt][3] * inv1);
    }
}

// ---------------- launch -----------------------------------------------------
extern "C" void kernel_launch(void* const* d_in, const int* in_sizes, int n_in,
                              void* d_out, int out_size)
{
    const float* x   = (const float*)d_in[0];
    const float* Wq  = (const float*)d_in[1];
    const float* Wk  = (const float*)d_in[2];
    const float* Wv  = (const float*)d_in[3];
    const float* Wo  = (const float*)d_in[4];
    const int*   pos = (const int*)d_in[5];
    float* out = (float*)d_out;

    __half *xhi, *wqhi, *wkhi, *wvhi, *wohi;
    __half *qhi, *khi, *vhi, *ohi;
    float2* ropeTab;
    cudaGetSymbolAddress((void**)&xhi,  g_xhi);
    cudaGetSymbolAddress((void**)&wqhi, g_wqhi);
    cudaGetSymbolAddress((void**)&wkhi, g_wkhi);
    cudaGetSymbolAddress((void**)&wvhi, g_wvhi);
    cudaGetSymbolAddress((void**)&wohi, g_wohi);
    cudaGetSymbolAddress((void**)&qhi,  g_Qhi);
    cudaGetSymbolAddress((void**)&khi,  g_Khi);
    cudaGetSymbolAddress((void**)&vhi,  g_Vhi);
    cudaGetSymbolAddress((void**)&ohi,  g_Ohi);
    cudaGetSymbolAddress((void**)&ropeTab, g_rope);

    cudaFuncSetAttribute(qkv_gemm_kernel,
                         cudaFuncAttributeMaxDynamicSharedMemorySize, GEMM_SMEM);
    cudaFuncSetAttribute(wo_gemm_kernel,
                         cudaFuncAttributeMaxDynamicSharedMemorySize, GEMM_SMEM);
    cudaFuncSetAttribute(attn_mma_kernel,
                         cudaFuncAttributeMaxDynamicSharedMemorySize, ATT_SMEM);

    // 1) fused split pass (fp16 conversion, MLP=4) + RoPE cos/sin table
    split_all_kernel<<<SPLIT_CTAS + ROPE_CTAS, 256>>>(x, Wq, Wk, Wv, Wo, pos,
                                                      xhi, wqhi, wkhi, wvhi, wohi,
                                                      ropeTab);

    // 2) persistent fused QKV projection (+RoPE table on Q,K), single-term
    qkv_gemm_kernel<<<QKV_GRID, 256, GEMM_SMEM>>>(xhi, wqhi, wkhi, wvhi,
                                                  qhi, khi, vhi, ropeTab);

    // 3) causal flash attention
    dim3 agrid(Sq / 128, Bsz * Hn);            // (16, 32)
    attn_mma_kernel<<<agrid, 256, ATT_SMEM>>>(qhi, khi, vhi, ohi);

    // 4) output projection (single-term)
    dim3 wogrid(Dm / BN, Mrows / BM);          // (8, 32)
    wo_gemm_kernel<<<wogrid, 256, GEMM_SMEM>>>(ohi, wohi, out);
}

// round 15
// speedup vs baseline: 1.0583x; 1.0583x over previous
#include <cuda_runtime.h>
#include <cuda_fp16.h>
#include <math.h>
#include <stdint.h>

// Problem constants (fixed by this dataset instance)
#define Bsz 2
#define Sq  2048
#define Dm  1024
#define Hn  16
#define Dk  64
#define Mrows (Bsz*Sq)   // 4096

// ---------------- scratch ----------------------------------------------------
__device__ __half g_xhi[Mrows*Dm];                     // x: fp16 hi only
__device__ __half g_wqhi[Dm*Dm];                       // weights: fp16 hi only
__device__ __half g_wkhi[Dm*Dm];
__device__ __half g_wvhi[Dm*Dm];
__device__ __half g_wohi[Dm*Dm];
__device__ __half g_Qhi[Mrows*Dm];                     // [B,H,S,Dk] fp16 hi
__device__ __half g_Khi[Mrows*Dm];
__device__ __half g_Vhi[Mrows*Dm];
__device__ __half g_Ohi[Mrows*Dm];                     // [B,S,D] fp16 hi
__device__ float2 g_rope[Mrows*(Dk/2)];                // [row, dk/2] = {cos, sin}

// ================= small PTX wrappers (portable, compute_103-safe) ===========
__device__ __forceinline__ uint32_t smem_u32(const void* p) {
    uint32_t a;
    asm("{ .reg .u64 t; cvta.to.shared.u64 t, %1; cvt.u32.u64 %0, t; }"
        : "=r"(a) : "l"(p));
    return a;
}
__device__ __forceinline__ void ldsm_x4(uint32_t addr, uint32_t r[4]) {
    asm volatile("ldmatrix.sync.aligned.m8n8.x4.shared.b16 {%0,%1,%2,%3}, [%4];"
                 : "=r"(r[0]), "=r"(r[1]), "=r"(r[2]), "=r"(r[3]) : "r"(addr));
}
__device__ __forceinline__ void ldsm_x4t(uint32_t addr, uint32_t r[4]) {
    asm volatile("ldmatrix.sync.aligned.m8n8.x4.trans.shared.b16 {%0,%1,%2,%3}, [%4];"
                 : "=r"(r[0]), "=r"(r[1]), "=r"(r[2]), "=r"(r[3]) : "r"(addr));
}
__device__ __forceinline__ void mma_f16(float c[4], const uint32_t a[4],
                                        const uint32_t b[2]) {
    asm volatile(
        "mma.sync.aligned.m16n8k16.row.col.f32.f16.f16.f32 "
        "{%0,%1,%2,%3}, {%4,%5,%6,%7}, {%8,%9}, {%0,%1,%2,%3};"
        : "+f"(c[0]), "+f"(c[1]), "+f"(c[2]), "+f"(c[3])
        : "r"(a[0]), "r"(a[1]), "r"(a[2]), "r"(a[3]), "r"(b[0]), "r"(b[1]));
}
__device__ __forceinline__ void cp16(uint32_t smem_addr, const void* gptr) {
    asm volatile("cp.async.cg.shared.global [%0], [%1], 16;"
                 :: "r"(smem_addr), "l"(gptr) : "memory");
}
#define CP_COMMIT() asm volatile("cp.async.commit_group;" ::: "memory")
#define CP_WAIT(n)  asm volatile("cp.async.wait_group %0;" :: "n"(n) : "memory")

__device__ __forceinline__ uint32_t pack_hf2(float x, float y) {
    __half2 t = __floats2half2_rn(x, y);
    return *reinterpret_cast<uint32_t*>(&t);
}

// ================= fused split pass + RoPE table ==============================
#define NX4 (Mrows*Dm/4)    // 1048576
#define NW4 (Dm*Dm/4)       // 262144
#define NTOT4 (NX4 + 4*NW4) // 2097152
#define SPLIT_STRIDE (NTOT4/4)          // 524288 threads
#define SPLIT_CTAS (SPLIT_STRIDE/256)   // 2048
#define ROPE_N (Mrows*(Dk/2))           // 131072
#define ROPE_CTAS (ROPE_N/256)          // 512

__global__ void __launch_bounds__(256)
split_all_kernel(const float* __restrict__ x,  const float* __restrict__ Wq,
                 const float* __restrict__ Wk, const float* __restrict__ Wv,
                 const float* __restrict__ Wo, const int* __restrict__ pos,
                 __half* __restrict__ xhi,
                 __half* __restrict__ wqhi, __half* __restrict__ wkhi,
                 __half* __restrict__ wvhi, __half* __restrict__ wohi,
                 float2* __restrict__ ropeTab)
{
    const int bid = blockIdx.x;
    if (bid < SPLIT_CTAS) {
        #pragma unroll
        for (int k = 0; k < 4; k++) {
            int i = bid * 256 + threadIdx.x + k * SPLIT_STRIDE;
            const float* src; __half* hi; int j;
            if (i < NX4) { src = x; hi = xhi; j = i; }
            else {
                int t = (i - NX4) >> 18;            // which weight (NW4 = 2^18)
                j = (i - NX4) & (NW4 - 1);
                if      (t == 0) { src = Wq; hi = wqhi; }
                else if (t == 1) { src = Wk; hi = wkhi; }
                else if (t == 2) { src = Wv; hi = wvhi; }
                else             { src = Wo; hi = wohi; }
            }
            float4 v = reinterpret_cast<const float4*>(src)[j];
            reinterpret_cast<uint2*>(hi)[j] =
                make_uint2(pack_hf2(v.x, v.y), pack_hf2(v.z, v.w));
        }
    } else {
        const int gid = (bid - SPLIT_CTAS) * 256 + threadIdx.x;   // 0..131071
        const int m   = gid >> 5;
        const int dkh = gid & 31;
        const float p = (float)pos[m];
        const float inv = exp2f((float)(2 * dkh) * (-13.287712379549449f / 64.0f));
        float sn, cs;
        sincosf(p * inv, &sn, &cs);
        ropeTab[gid] = make_float2(cs, sn);
    }
}

// ================= shared GEMM machinery (single-term fp16) ===================
#define BM 128
#define BN 128
#define BK 32
#define KT_ITERS (Dm/BK)              // 32
#define TPITCH 80
#define TILE_BYTES (128*TPITCH)        // 10240
#define STAGE_BYTES (2*TILE_BYTES)     // Ahi|Bhi = 20480
#define NSTAGE 4
#define GEMM_SMEM (NSTAGE*STAGE_BYTES) // 81920  (2 CTAs/SM)

struct GemmCore {
    uint32_t sbase;
    int lane, warp_m, warp_n, m0, n0;
    const __half *Ahi, *Bhi;
    int r0a, c0, r1a;

    __device__ __forceinline__ void issue_stage(int stage, int kt) {
        const int kc = kt * BK;
        const uint32_t sb = sbase + stage * STAGE_BYTES;
        cp16(sb + (uint32_t)(r0a * TPITCH + c0 * 16),
             Ahi + (size_t)(m0 + r0a) * Dm + kc + c0 * 8);
        cp16(sb + (uint32_t)(r1a * TPITCH + c0 * 16),
             Ahi + (size_t)(m0 + r1a) * Dm + kc + c0 * 8);
        cp16(sb + TILE_BYTES + (uint32_t)(r0a * TPITCH + c0 * 16),
             Bhi + (size_t)(n0 + r0a) * Dm + kc + c0 * 8);
        cp16(sb + TILE_BYTES + (uint32_t)(r1a * TPITCH + c0 * 16),
             Bhi + (size_t)(n0 + r1a) * Dm + kc + c0 * 8);
        CP_COMMIT();
    }

    __device__ __forceinline__ void mainloop(float acc[4][4][4]) {
        issue_stage(0, 0);
        issue_stage(1, 1);
        issue_stage(2, 2);
        for (int kt = 0; kt < KT_ITERS; kt++) {
            if (kt + 2 < KT_ITERS)      { CP_WAIT(2); }
            else if (kt + 1 < KT_ITERS) { CP_WAIT(1); }
            else                        { CP_WAIT(0); }
            __syncthreads();
            if (kt + 3 < KT_ITERS) issue_stage((kt + 3) & 3, kt + 3);

            const uint32_t sb = sbase + (kt & 3) * STAGE_BYTES;
            const uint32_t sAhi = sb;
            const uint32_t sBhi = sb + TILE_BYTES;

            #pragma unroll
            for (int ks = 0; ks < 2; ks++) {
                const int chunk = ks * 2;
                // paired x4 B loads: contiguous fragment pairs, zero unpack MOVs.
                // lanes 0-7: nt=2pr rows, k-half0 | 8-15: nt=2pr, k-half1
                // lanes 16-23: nt=2pr+1, k-half0 | 24-31: nt=2pr+1, k-half1
                uint32_t bq[2][4];
                #pragma unroll
                for (int pr = 0; pr < 2; pr++) {
                    const int brow = warp_n * 32 + pr * 16 + ((lane >> 4) & 1) * 8 + (lane & 7);
                    const uint32_t boff =
                        (uint32_t)(brow * TPITCH + (chunk + ((lane >> 3) & 1)) * 16);
                    ldsm_x4(sBhi + boff, bq[pr]);
                }
                #pragma unroll
                for (int mt = 0; mt < 4; mt++) {
                    uint32_t ahi[4];
                    const int arow = warp_m * 64 + mt * 16 + (lane & 15);
                    const uint32_t aoff = (uint32_t)(arow * TPITCH + (chunk + (lane >> 4)) * 16);
                    ldsm_x4(sAhi + aoff, ahi);
                    mma_f16(acc[mt][0], ahi, bq[0]);
                    mma_f16(acc[mt][1], ahi, bq[0] + 2);
                    mma_f16(acc[mt][2], ahi, bq[1]);
                    mma_f16(acc[mt][3], ahi, bq[1] + 2);
                }
            }
        }
    }
};

// ---- fused QKV GEMM: one launch computes Q, K, V projections -----------------
__global__ void __launch_bounds__(256, 2)
qkv_gemm_kernel(const __half* __restrict__ xhi,
                const __half* __restrict__ wqhi, const __half* __restrict__ wkhi,
                const __half* __restrict__ wvhi,
                __half* __restrict__ qhi, __half* __restrict__ khi,
                __half* __restrict__ vhi, const float2* __restrict__ ropeTab)
{
    extern __shared__ char sm[];
    const int tid  = threadIdx.x;
    const int wsel = blockIdx.x >> 3;

    GemmCore gc;
    gc.sbase = smem_u32(sm);
    gc.lane = tid & 31;
    gc.warp_m = (tid >> 5) & 1; gc.warp_n = tid >> 6;
    gc.n0 = (blockIdx.x & 7) * BN;
    gc.m0 = blockIdx.y * BM;
    gc.Ahi = xhi;
    gc.r0a = tid >> 2; gc.c0 = tid & 3; gc.r1a = (tid + 256) >> 2;

    __half* Chi;
    bool rope;
    if (wsel == 0)      { gc.Bhi = wqhi; Chi = qhi; rope = true;  }
    else if (wsel == 1) { gc.Bhi = wkhi; Chi = khi; rope = true;  }
    else                { gc.Bhi = wvhi; Chi = vhi; rope = false; }

    float acc[4][4][4];
    #pragma unroll
    for (int i = 0; i < 4; i++)
        #pragma unroll
        for (int j = 0; j < 4; j++)
            #pragma unroll
            for (int v = 0; v < 4; v++) acc[i][j][v] = 0.f;

    gc.mainloop(acc);

    // epilogue: fused RoPE (table lookup) + fp16 hi store to [B,H,S,Dk]
    const int lane = gc.lane;
    #pragma unroll
    for (int mt = 0; mt < 4; mt++) {
        #pragma unroll
        for (int half = 0; half < 2; half++) {
            const int row = gc.m0 + gc.warp_m * 64 + mt * 16 + (lane >> 2) + half * 8;
            const int b = row >> 11;
            const int s = row & (Sq - 1);
            #pragma unroll
            for (int nt = 0; nt < 4; nt++) {
                const int col = gc.n0 + gc.warp_n * 32 + nt * 8 + (lane & 3) * 2;  // even
                float e = acc[mt][nt][half * 2];
                float o = acc[mt][nt][half * 2 + 1];
                if (rope) {
                    const int dkh = (col & (Dk - 1)) >> 1;
                    const float2 cssn = ropeTab[row * (Dk / 2) + dkh];
                    const float re = e * cssn.x - o * cssn.y;
                    const float ro = e * cssn.y + o * cssn.x;
                    e = re; o = ro;
                }
                const int h  = col >> 6;
                const int dk = col & (Dk - 1);
                const size_t idx = ((size_t)(b * Hn + h) * Sq + s) * Dk + dk;
                *reinterpret_cast<uint32_t*>(Chi + idx) = pack_hf2(e, o);
            }
        }
    }
}

// ---- output projection GEMM: single-term, fp32 out ----------------------------
__global__ void __launch_bounds__(256, 2)
wo_gemm_kernel(const __half* __restrict__ Ahi, const __half* __restrict__ Bhi,
               float* __restrict__ C)
{
    extern __shared__ char sm[];
    const int tid = threadIdx.x;

    GemmCore gc;
    gc.sbase = smem_u32(sm);
    gc.lane = tid & 31;
    gc.warp_m = (tid >> 5) & 1; gc.warp_n = tid >> 6;
    gc.n0 = blockIdx.x * BN;
    gc.m0 = blockIdx.y * BM;
    gc.Ahi = Ahi; gc.Bhi = Bhi;
    gc.r0a = tid >> 2; gc.c0 = tid & 3; gc.r1a = (tid + 256) >> 2;

    float acc[4][4][4];
    #pragma unroll
    for (int i = 0; i < 4; i++)
        #pragma unroll
        for (int j = 0; j < 4; j++)
            #pragma unroll
            for (int v = 0; v < 4; v++) acc[i][j][v] = 0.f;

    gc.mainloop(acc);

    const int lane = gc.lane;
    #pragma unroll
    for (int mt = 0; mt < 4; mt++) {
        #pragma unroll
        for (int half = 0; half < 2; half++) {
            const int row = gc.m0 + gc.warp_m * 64 + mt * 16 + (lane >> 2) + half * 8;
            #pragma unroll
            for (int nt = 0; nt < 4; nt++) {
                const int col = gc.n0 + gc.warp_n * 32 + nt * 8 + (lane & 3) * 2;
                float* dst = C + (size_t)row * Dm + col;
                *reinterpret_cast<float2*>(dst) =
                    make_float2(acc[mt][nt][half * 2], acc[mt][nt][half * 2 + 1]);
            }
        }
    }
}

// ================= tensor-core causal flash attention (pure fp16) =============
#define ATPITCH 144
#define AT_TILE (64*ATPITCH)          // 9216
#define AT_STAGE (2*AT_TILE)          // Khi|Vhi = 18432
#define AT_NSTAGE 3
#define ATT_SMEM (AT_NSTAGE*AT_STAGE) // 55296  (2 CTAs/SM)

__global__ void __launch_bounds__(256, 2)
attn_mma_kernel(const __half* __restrict__ Qhi,
                const __half* __restrict__ Khi, const __half* __restrict__ Vhi,
                __half* __restrict__ Ohi)
{
    extern __shared__ char sm[];
    const uint32_t sbase = smem_u32(sm);

    const int tid  = threadIdx.x;
    const int lane = tid & 31;
    const int w    = tid >> 5;
    const int bh   = blockIdx.y;
    const int qt   = (int)gridDim.x - 1 - (int)blockIdx.x;   // big tiles first
    const int q0   = qt * 128;
    const int NT   = 2 * qt + 2;                             // key tiles (64 each)

    const size_t kvbase = (size_t)bh * Sq;

    // --- Q fragments (direct gmem gather, once) ------------------------------
    const int r  = q0 + w * 16 + (lane >> 2);
    const int dc = 2 * (lane & 3);
    uint32_t qh[4][4];
    #pragma unroll
    for (int c = 0; c < 4; c++) {
        const int d = c * 16 + dc;
        const size_t i00 = (kvbase + r) * Dk + d;
        const size_t i10 = (kvbase + r + 8) * Dk + d;
        qh[c][0] = *reinterpret_cast<const uint32_t*>(Qhi + i00);
        qh[c][1] = *reinterpret_cast<const uint32_t*>(Qhi + i10);
        qh[c][2] = *reinterpret_cast<const uint32_t*>(Qhi + i00 + 8);
        qh[c][3] = *reinterpret_cast<const uint32_t*>(Qhi + i10 + 8);
    }

    const __half* gkv[2] = {Khi, Vhi};
    auto issue_kv = [&](int stage, int it) {
        const int k0 = it * 64;
        const uint32_t sb = sbase + stage * AT_STAGE;
        #pragma unroll
        for (int i = 0; i < 4; i++) {
            const int c = tid + i * 256;          // 0..1023
            const int t = c >> 9;                 // tile 0..1
            const int rr = (c >> 3) & 63;         // row 0..63
            const int cl = c & 7;                 // 16B chunk 0..7
            cp16(sb + t * AT_TILE + (uint32_t)(rr * ATPITCH + cl * 16),
                 gkv[t] + (kvbase + k0 + rr) * Dk + cl * 8);
        }
        CP_COMMIT();
    };

    float o[8][4];
    #pragma unroll
    for (int nt = 0; nt < 8; nt++)
        #pragma unroll
        for (int j = 0; j < 4; j++) o[nt][j] = 0.f;
    float m0 = -1e30f, m1 = -1e30f, l0 = 0.f, l1 = 0.f;

    issue_kv(0, 0);
    issue_kv(1, 1);

    const float SCL = 0.125f * 1.4426950408889634f;  // scale * log2(e)

    for (int it = 0; it < NT; it++) {
        if (it + 1 < NT) { CP_WAIT(1); } else { CP_WAIT(0); }
        __syncthreads();
        if (it + 2 < NT) issue_kv((it + 2) % AT_NSTAGE, it + 2);  // single-sync pipeline

        const uint32_t sb  = sbase + (it % AT_NSTAGE) * AT_STAGE;
        const uint32_t sKh = sb;
        const uint32_t sVh = sb + AT_TILE;
        const int k0 = it * 64;

        // ---- S = Q K^T (paired x4 K loads) ------------------------------------
        float s[8][4];
        #pragma unroll
        for (int nt = 0; nt < 8; nt++)
            #pragma unroll
            for (int j = 0; j < 4; j++) s[nt][j] = 0.f;

        #pragma unroll
        for (int c = 0; c < 4; c++) {
            #pragma unroll
            for (int pr = 0; pr < 4; pr++) {
                uint32_t tmp[4];
                const int brow = pr * 16 + ((lane >> 4) & 1) * 8 + (lane & 7);
                const uint32_t boff =
                    (uint32_t)(brow * ATPITCH + (c * 2 + ((lane >> 3) & 1)) * 16);
                ldsm_x4(sKh + boff, tmp);
                mma_f16(s[2 * pr],     qh[c], tmp);
                mma_f16(s[2 * pr + 1], qh[c], tmp + 2);
            }
        }

        // ---- online softmax (exp2 domain) ------------------------------------
        const bool need_mask = (k0 + 63 > q0);
        float t0 = -1e30f, t1 = -1e30f;
        #pragma unroll
        for (int nt = 0; nt < 8; nt++) {
            #pragma unroll
            for (int j = 0; j < 4; j++) {
                float t = s[nt][j] * SCL;
                if (need_mask) {
                    const int col = k0 + nt * 8 + dc + (j & 1);
                    const int row = (j < 2) ? r : r + 8;
                    if (col > row) t = -1e30f;
                }
                s[nt][j] = t;
                if (j < 2) t0 = fmaxf(t0, t); else t1 = fmaxf(t1, t);
            }
        }
        t0 = fmaxf(t0, __shfl_xor_sync(0xffffffffu, t0, 1));
        t0 = fmaxf(t0, __shfl_xor_sync(0xffffffffu, t0, 2));
        t1 = fmaxf(t1, __shfl_xor_sync(0xffffffffu, t1, 1));
        t1 = fmaxf(t1, __shfl_xor_sync(0xffffffffu, t1, 2));
        const float mn0 = fmaxf(m0, t0), mn1 = fmaxf(m1, t1);
        const float corr0 = exp2f(m0 - mn0), corr1 = exp2f(m1 - mn1);
        m0 = mn0; m1 = mn1;

        float ps0 = 0.f, ps1 = 0.f;
        #pragma unroll
        for (int nt = 0; nt < 8; nt++) {
            s[nt][0] = exp2f(s[nt][0] - m0);
            s[nt][1] = exp2f(s[nt][1] - m0);
            s[nt][2] = exp2f(s[nt][2] - m1);
            s[nt][3] = exp2f(s[nt][3] - m1);
            ps0 += s[nt][0] + s[nt][1];
            ps1 += s[nt][2] + s[nt][3];
        }
        ps0 += __shfl_xor_sync(0xffffffffu, ps0, 1);
        ps0 += __shfl_xor_sync(0xffffffffu, ps0, 2);
        ps1 += __shfl_xor_sync(0xffffffffu, ps1, 1);
        ps1 += __shfl_xor_sync(0xffffffffu, ps1, 2);
        l0 = l0 * corr0 + ps0;
        l1 = l1 * corr1 + ps1;

        #pragma unroll
        for (int nt = 0; nt < 8; nt++) {
            o[nt][0] *= corr0; o[nt][1] *= corr0;
            o[nt][2] *= corr1; o[nt][3] *= corr1;
        }

        // ---- O += P V (paired x4 trans V loads) --------------------------------
        #pragma unroll
        for (int u = 0; u < 4; u++) {
            uint32_t aph[4];
            aph[0] = pack_hf2(s[2*u][0],   s[2*u][1]);
            aph[1] = pack_hf2(s[2*u][2],   s[2*u][3]);
            aph[2] = pack_hf2(s[2*u+1][0], s[2*u+1][1]);
            aph[3] = pack_hf2(s[2*u+1][2], s[2*u+1][3]);
            #pragma unroll
            for (int pr = 0; pr < 4; pr++) {
                uint32_t tmp[4];
                const uint32_t voff =
                    (uint32_t)((u * 16 + (lane & 15)) * ATPITCH +
                               (2 * pr + ((lane >> 4) & 1)) * 16);
                ldsm_x4t(sVh + voff, tmp);
                mma_f16(o[2 * pr],     aph, tmp);
                mma_f16(o[2 * pr + 1], aph, tmp + 2);
            }
        }
    }

    // ---- epilogue: normalize, fp16 hi store, write [B,S,D] -------------------
    const float inv0 = 1.0f / l0, inv1 = 1.0f / l1;
    const int b = bh >> 4, h = bh & 15;
    const size_t base0 = ((size_t)b * Sq + r) * Dm + h * Dk;
    const size_t base1 = ((size_t)b * Sq + r + 8) * Dm + h * Dk;
    #pragma unroll
    for (int nt = 0; nt < 8; nt++) {
        const int col = nt * 8 + dc;
        *reinterpret_cast<uint32_t*>(Ohi + base0 + col) =
            pack_hf2(o[nt][0] * inv0, o[nt][1] * inv0);
        *reinterpret_cast<uint32_t*>(Ohi + base1 + col) =
            pack_hf2(o[nt][2] * inv1, o[nt][3] * inv1);
    }
}

// ---------------- launch -----------------------------------------------------
extern "C" void kernel_launch(void* const* d_in, const int* in_sizes, int n_in,
                              void* d_out, int out_size)
{
    const float* x   = (const float*)d_in[0];
    const float* Wq  = (const float*)d_in[1];
    const float* Wk  = (const float*)d_in[2];
    const float* Wv  = (const float*)d_in[3];
    const float* Wo  = (const float*)d_in[4];
    const int*   pos = (const int*)d_in[5];
    float* out = (float*)d_out;

    __half *xhi, *wqhi, *wkhi, *wvhi, *wohi;
    __half *qhi, *khi, *vhi, *ohi;
    float2* ropeTab;
    cudaGetSymbolAddress((void**)&xhi,  g_xhi);
    cudaGetSymbolAddress((void**)&wqhi, g_wqhi);
    cudaGetSymbolAddress((void**)&wkhi, g_wkhi);
    cudaGetSymbolAddress((void**)&wvhi, g_wvhi);
    cudaGetSymbolAddress((void**)&wohi, g_wohi);
    cudaGetSymbolAddress((void**)&qhi,  g_Qhi);
    cudaGetSymbolAddress((void**)&khi,  g_Khi);
    cudaGetSymbolAddress((void**)&vhi,  g_Vhi);
    cudaGetSymbolAddress((void**)&ohi,  g_Ohi);
    cudaGetSymbolAddress((void**)&ropeTab, g_rope);

    cudaFuncSetAttribute(qkv_gemm_kernel,
                         cudaFuncAttributeMaxDynamicSharedMemorySize, GEMM_SMEM);
    cudaFuncSetAttribute(wo_gemm_kernel,
                         cudaFuncAttributeMaxDynamicSharedMemorySize, GEMM_SMEM);
    cudaFuncSetAttribute(attn_mma_kernel,
                         cudaFuncAttributeMaxDynamicSharedMemorySize, ATT_SMEM);

    // 1) fused split pass (fp16 conversion, MLP=4) + RoPE cos/sin table
    split_all_kernel<<<SPLIT_CTAS + ROPE_CTAS, 256>>>(x, Wq, Wk, Wv, Wo, pos,
                                                      xhi, wqhi, wkhi, wvhi, wohi,
                                                      ropeTab);

    // 2) fused QKV projection (+RoPE table on Q,K), single-term
    dim3 qkvgrid(3 * (Dm / BN), Mrows / BM);   // (24, 32)
    qkv_gemm_kernel<<<qkvgrid, 256, GEMM_SMEM>>>(xhi, wqhi, wkhi, wvhi,
                                                 qhi, khi, vhi, ropeTab);

    // 3) causal flash attention
    dim3 agrid(Sq / 128, Bsz * Hn);            // (16, 32)
    attn_mma_kernel<<<agrid, 256, ATT_SMEM>>>(qhi, khi, vhi, ohi);

    // 4) output projection (single-term)
    dim3 wogrid(Dm / BN, Mrows / BM);          // (8, 32)
    wo_gemm_kernel<<<wogrid, 256, GEMM_SMEM>>>(ohi, wohi, out);
}

// round 16
// speedup vs baseline: 1.0651x; 1.0064x over previous
#include <cuda_runtime.h>
#include <cuda_fp16.h>
#include <math.h>
#include <stdint.h>

// Problem constants (fixed by this dataset instance)
#define Bsz 2
#define Sq  2048
#define Dm  1024
#define Hn  16
#define Dk  64
#define Mrows (Bsz*Sq)   // 4096

// ---------------- scratch ----------------------------------------------------
__device__ __half g_xhi[Mrows*Dm];                     // x: fp16 hi only
__device__ __half g_wqhi[Dm*Dm];                       // weights: fp16 hi only
__device__ __half g_wkhi[Dm*Dm];
__device__ __half g_wvhi[Dm*Dm];
__device__ __half g_wohi[Dm*Dm];
__device__ __half g_Qhi[Mrows*Dm];                     // [B,H,S,Dk] fp16 hi (pre-scaled)
__device__ __half g_Khi[Mrows*Dm];
__device__ __half g_Vhi[Mrows*Dm];
__device__ __half g_Ohi[Mrows*Dm];                     // [B,S,D] fp16 hi
__device__ float2 g_rope[Mrows*(Dk/2)];                // [row, dk/2] = {cos, sin}

// ================= small PTX wrappers (portable, compute_103-safe) ===========
__device__ __forceinline__ uint32_t smem_u32(const void* p) {
    uint32_t a;
    asm("{ .reg .u64 t; cvta.to.shared.u64 t, %1; cvt.u32.u64 %0, t; }"
        : "=r"(a) : "l"(p));
    return a;
}
__device__ __forceinline__ void ldsm_x4(uint32_t addr, uint32_t r[4]) {
    asm volatile("ldmatrix.sync.aligned.m8n8.x4.shared.b16 {%0,%1,%2,%3}, [%4];"
                 : "=r"(r[0]), "=r"(r[1]), "=r"(r[2]), "=r"(r[3]) : "r"(addr));
}
__device__ __forceinline__ void ldsm_x4t(uint32_t addr, uint32_t r[4]) {
    asm volatile("ldmatrix.sync.aligned.m8n8.x4.trans.shared.b16 {%0,%1,%2,%3}, [%4];"
                 : "=r"(r[0]), "=r"(r[1]), "=r"(r[2]), "=r"(r[3]) : "r"(addr));
}
__device__ __forceinline__ void mma_f16(float c[4], const uint32_t a[4],
                                        const uint32_t b[2]) {
    asm volatile(
        "mma.sync.aligned.m16n8k16.row.col.f32.f16.f16.f32 "
        "{%0,%1,%2,%3}, {%4,%5,%6,%7}, {%8,%9}, {%0,%1,%2,%3};"
        : "+f"(c[0]), "+f"(c[1]), "+f"(c[2]), "+f"(c[3])
        : "r"(a[0]), "r"(a[1]), "r"(a[2]), "r"(a[3]), "r"(b[0]), "r"(b[1]));
}
__device__ __forceinline__ void cp16(uint32_t smem_addr, const void* gptr) {
    asm volatile("cp.async.cg.shared.global [%0], [%1], 16;"
                 :: "r"(smem_addr), "l"(gptr) : "memory");
}
#define CP_COMMIT() asm volatile("cp.async.commit_group;" ::: "memory")
#define CP_WAIT(n)  asm volatile("cp.async.wait_group %0;" :: "n"(n) : "memory")

__device__ __forceinline__ uint32_t pack_hf2(float x, float y) {
    __half2 t = __floats2half2_rn(x, y);
    return *reinterpret_cast<uint32_t*>(&t);
}
__device__ __forceinline__ float ex2f(float x) {   // raw MUFU.EX2, 1 instr
    float y;
    asm("ex2.approx.f32 %0, %1;" : "=f"(y) : "f"(x));
    return y;
}

// ================= fused split pass + RoPE table ==============================
#define NX4 (Mrows*Dm/4)    // 1048576
#define NW4 (Dm*Dm/4)       // 262144
#define NTOT4 (NX4 + 4*NW4) // 2097152
#define SPLIT_STRIDE (NTOT4/4)          // 524288 threads
#define SPLIT_CTAS (SPLIT_STRIDE/256)   // 2048
#define ROPE_N (Mrows*(Dk/2))           // 131072
#define ROPE_CTAS (ROPE_N/256)          // 512

__global__ void __launch_bounds__(256)
split_all_kernel(const float* __restrict__ x,  const float* __restrict__ Wq,
                 const float* __restrict__ Wk, const float* __restrict__ Wv,
                 const float* __restrict__ Wo, const int* __restrict__ pos,
                 __half* __restrict__ xhi,
                 __half* __restrict__ wqhi, __half* __restrict__ wkhi,
                 __half* __restrict__ wvhi, __half* __restrict__ wohi,
                 float2* __restrict__ ropeTab)
{
    const int bid = blockIdx.x;
    if (bid < SPLIT_CTAS) {
        #pragma unroll
        for (int k = 0; k < 4; k++) {
            int i = bid * 256 + threadIdx.x + k * SPLIT_STRIDE;
            const float* src; __half* hi; int j;
            if (i < NX4) { src = x; hi = xhi; j = i; }
            else {
                int t = (i - NX4) >> 18;            // which weight (NW4 = 2^18)
                j = (i - NX4) & (NW4 - 1);
                if      (t == 0) { src = Wq; hi = wqhi; }
                else if (t == 1) { src = Wk; hi = wkhi; }
                else if (t == 2) { src = Wv; hi = wvhi; }
                else             { src = Wo; hi = wohi; }
            }
            float4 v = reinterpret_cast<const float4*>(src)[j];
            reinterpret_cast<uint2*>(hi)[j] =
                make_uint2(pack_hf2(v.x, v.y), pack_hf2(v.z, v.w));
        }
    } else {
        const int gid = (bid - SPLIT_CTAS) * 256 + threadIdx.x;   // 0..131071
        const int m   = gid >> 5;
        const int dkh = gid & 31;
        const float p = (float)pos[m];
        const float inv = exp2f((float)(2 * dkh) * (-13.287712379549449f / 64.0f));
        float sn, cs;
        sincosf(p * inv, &sn, &cs);
        ropeTab[gid] = make_float2(cs, sn);
    }
}

// ================= shared GEMM machinery (single-term fp16) ===================
#define BM 128
#define BN 128
#define BK 32
#define KT_ITERS (Dm/BK)              // 32
#define TPITCH 80
#define TILE_BYTES (128*TPITCH)        // 10240
#define STAGE_BYTES (2*TILE_BYTES)     // Ahi|Bhi = 20480
#define NSTAGE 4
#define GEMM_SMEM (NSTAGE*STAGE_BYTES) // 81920  (2 CTAs/SM)

struct GemmCore {
    uint32_t sbase;
    int lane, warp_m, warp_n, m0, n0;
    const __half *Ahi, *Bhi;
    int r0a, c0, r1a;

    __device__ __forceinline__ void issue_stage(int stage, int kt) {
        const int kc = kt * BK;
        const uint32_t sb = sbase + stage * STAGE_BYTES;
        cp16(sb + (uint32_t)(r0a * TPITCH + c0 * 16),
             Ahi + (size_t)(m0 + r0a) * Dm + kc + c0 * 8);
        cp16(sb + (uint32_t)(r1a * TPITCH + c0 * 16),
             Ahi + (size_t)(m0 + r1a) * Dm + kc + c0 * 8);
        cp16(sb + TILE_BYTES + (uint32_t)(r0a * TPITCH + c0 * 16),
             Bhi + (size_t)(n0 + r0a) * Dm + kc + c0 * 8);
        cp16(sb + TILE_BYTES + (uint32_t)(r1a * TPITCH + c0 * 16),
             Bhi + (size_t)(n0 + r1a) * Dm + kc + c0 * 8);
        CP_COMMIT();
    }

    __device__ __forceinline__ void mainloop(float acc[4][4][4]) {
        issue_stage(0, 0);
        issue_stage(1, 1);
        issue_stage(2, 2);
        for (int kt = 0; kt < KT_ITERS; kt++) {
            if (kt + 2 < KT_ITERS)      { CP_WAIT(2); }
            else if (kt + 1 < KT_ITERS) { CP_WAIT(1); }
            else                        { CP_WAIT(0); }
            __syncthreads();
            if (kt + 3 < KT_ITERS) issue_stage((kt + 3) & 3, kt + 3);

            const uint32_t sb = sbase + (kt & 3) * STAGE_BYTES;
            const uint32_t sAhi = sb;
            const uint32_t sBhi = sb + TILE_BYTES;

            #pragma unroll
            for (int ks = 0; ks < 2; ks++) {
                const int chunk = ks * 2;
                uint32_t bq[2][4];
                #pragma unroll
                for (int pr = 0; pr < 2; pr++) {
                    const int brow = warp_n * 32 + pr * 16 + ((lane >> 4) & 1) * 8 + (lane & 7);
                    const uint32_t boff =
                        (uint32_t)(brow * TPITCH + (chunk + ((lane >> 3) & 1)) * 16);
                    ldsm_x4(sBhi + boff, bq[pr]);
                }
                #pragma unroll
                for (int mt = 0; mt < 4; mt++) {
                    uint32_t ahi[4];
                    const int arow = warp_m * 64 + mt * 16 + (lane & 15);
                    const uint32_t aoff = (uint32_t)(arow * TPITCH + (chunk + (lane >> 4)) * 16);
                    ldsm_x4(sAhi + aoff, ahi);
                    mma_f16(acc[mt][0], ahi, bq[0]);
                    mma_f16(acc[mt][1], ahi, bq[0] + 2);
                    mma_f16(acc[mt][2], ahi, bq[1]);
                    mma_f16(acc[mt][3], ahi, bq[1] + 2);
                }
            }
        }
    }
};

// ---- fused QKV GEMM: one launch computes Q, K, V projections -----------------
// Q is pre-scaled by SCL = 0.125*log2(e) so attention skips per-score scaling.
__global__ void __launch_bounds__(256, 2)
qkv_gemm_kernel(const __half* __restrict__ xhi,
                const __half* __restrict__ wqhi, const __half* __restrict__ wkhi,
                const __half* __restrict__ wvhi,
                __half* __restrict__ qhi, __half* __restrict__ khi,
                __half* __restrict__ vhi, const float2* __restrict__ ropeTab)
{
    extern __shared__ char sm[];
    const int tid  = threadIdx.x;
    const int wsel = blockIdx.x >> 3;

    GemmCore gc;
    gc.sbase = smem_u32(sm);
    gc.lane = tid & 31;
    gc.warp_m = (tid >> 5) & 1; gc.warp_n = tid >> 6;
    gc.n0 = (blockIdx.x & 7) * BN;
    gc.m0 = blockIdx.y * BM;
    gc.Ahi = xhi;
    gc.r0a = tid >> 2; gc.c0 = tid & 3; gc.r1a = (tid + 256) >> 2;

    __half* Chi;
    bool rope;
    float oscale;
    if (wsel == 0)      { gc.Bhi = wqhi; Chi = qhi; rope = true;
                          oscale = 0.125f * 1.4426950408889634f; }
    else if (wsel == 1) { gc.Bhi = wkhi; Chi = khi; rope = true;  oscale = 1.f; }
    else                { gc.Bhi = wvhi; Chi = vhi; rope = false; oscale = 1.f; }

    float acc[4][4][4];
    #pragma unroll
    for (int i = 0; i < 4; i++)
        #pragma unroll
        for (int j = 0; j < 4; j++)
            #pragma unroll
            for (int v = 0; v < 4; v++) acc[i][j][v] = 0.f;

    gc.mainloop(acc);

    // epilogue: fused RoPE (table lookup) + optional scale + fp16 store
    const int lane = gc.lane;
    #pragma unroll
    for (int mt = 0; mt < 4; mt++) {
        #pragma unroll
        for (int half = 0; half < 2; half++) {
            const int row = gc.m0 + gc.warp_m * 64 + mt * 16 + (lane >> 2) + half * 8;
            const int b = row >> 11;
            const int s = row & (Sq - 1);
            #pragma unroll
            for (int nt = 0; nt < 4; nt++) {
                const int col = gc.n0 + gc.warp_n * 32 + nt * 8 + (lane & 3) * 2;  // even
                float e = acc[mt][nt][half * 2];
                float o = acc[mt][nt][half * 2 + 1];
                if (rope) {
                    const int dkh = (col & (Dk - 1)) >> 1;
                    const float2 cssn = ropeTab[row * (Dk / 2) + dkh];
                    const float re = e * cssn.x - o * cssn.y;
                    const float ro = e * cssn.y + o * cssn.x;
                    e = re * oscale; o = ro * oscale;
                }
                const int h  = col >> 6;
                const int dk = col & (Dk - 1);
                const size_t idx = ((size_t)(b * Hn + h) * Sq + s) * Dk + dk;
                *reinterpret_cast<uint32_t*>(Chi + idx) = pack_hf2(e, o);
            }
        }
    }
}

// ---- output projection GEMM: single-term, fp32 out ----------------------------
__global__ void __launch_bounds__(256, 2)
wo_gemm_kernel(const __half* __restrict__ Ahi, const __half* __restrict__ Bhi,
               float* __restrict__ C)
{
    extern __shared__ char sm[];
    const int tid = threadIdx.x;

    GemmCore gc;
    gc.sbase = smem_u32(sm);
    gc.lane = tid & 31;
    gc.warp_m = (tid >> 5) & 1; gc.warp_n = tid >> 6;
    gc.n0 = blockIdx.x * BN;
    gc.m0 = blockIdx.y * BM;
    gc.Ahi = Ahi; gc.Bhi = Bhi;
    gc.r0a = tid >> 2; gc.c0 = tid & 3; gc.r1a = (tid + 256) >> 2;

    float acc[4][4][4];
    #pragma unroll
    for (int i = 0; i < 4; i++)
        #pragma unroll
        for (int j = 0; j < 4; j++)
            #pragma unroll
            for (int v = 0; v < 4; v++) acc[i][j][v] = 0.f;

    gc.mainloop(acc);

    const int lane = gc.lane;
    #pragma unroll
    for (int mt = 0; mt < 4; mt++) {
        #pragma unroll
        for (int half = 0; half < 2; half++) {
            const int row = gc.m0 + gc.warp_m * 64 + mt * 16 + (lane >> 2) + half * 8;
            #pragma unroll
            for (int nt = 0; nt < 4; nt++) {
                const int col = gc.n0 + gc.warp_n * 32 + nt * 8 + (lane & 3) * 2;
                float* dst = C + (size_t)row * Dm + col;
                *reinterpret_cast<float2*>(dst) =
                    make_float2(acc[mt][nt][half * 2], acc[mt][nt][half * 2 + 1]);
            }
        }
    }
}

// ================= tensor-core causal flash attention (pure fp16) =============
// Q pre-scaled; exps via raw MUFU.EX2; rescale skipped when max unchanged.
#define ATPITCH 144
#define AT_TILE (64*ATPITCH)          // 9216
#define AT_STAGE (2*AT_TILE)          // Khi|Vhi = 18432
#define AT_NSTAGE 3
#define ATT_SMEM (AT_NSTAGE*AT_STAGE) // 55296  (2 CTAs/SM)

__global__ void __launch_bounds__(256, 2)
attn_mma_kernel(const __half* __restrict__ Qhi,
                const __half* __restrict__ Khi, const __half* __restrict__ Vhi,
                __half* __restrict__ Ohi)
{
    extern __shared__ char sm[];
    const uint32_t sbase = smem_u32(sm);

    const int tid  = threadIdx.x;
    const int lane = tid & 31;
    const int w    = tid >> 5;
    const int bh   = blockIdx.y;
    const int qt   = (int)gridDim.x - 1 - (int)blockIdx.x;   // big tiles first
    const int q0   = qt * 128;
    const int NT   = 2 * qt + 2;                             // key tiles (64 each)

    const size_t kvbase = (size_t)bh * Sq;

    // --- Q fragments (direct gmem gather, once) ------------------------------
    const int r  = q0 + w * 16 + (lane >> 2);
    const int dc = 2 * (lane & 3);
    uint32_t qh[4][4];
    #pragma unroll
    for (int c = 0; c < 4; c++) {
        const int d = c * 16 + dc;
        const size_t i00 = (kvbase + r) * Dk + d;
        const size_t i10 = (kvbase + r + 8) * Dk + d;
        qh[c][0] = *reinterpret_cast<const uint32_t*>(Qhi + i00);
        qh[c][1] = *reinterpret_cast<const uint32_t*>(Qhi + i10);
        qh[c][2] = *reinterpret_cast<const uint32_t*>(Qhi + i00 + 8);
        qh[c][3] = *reinterpret_cast<const uint32_t*>(Qhi + i10 + 8);
    }

    const __half* gkv[2] = {Khi, Vhi};
    auto issue_kv = [&](int stage, int it) {
        const int k0 = it * 64;
        const uint32_t sb = sbase + stage * AT_STAGE;
        #pragma unroll
        for (int i = 0; i < 4; i++) {
            const int c = tid + i * 256;          // 0..1023
            const int t = c >> 9;                 // tile 0..1
            const int rr = (c >> 3) & 63;         // row 0..63
            const int cl = c & 7;                 // 16B chunk 0..7
            cp16(sb + t * AT_TILE + (uint32_t)(rr * ATPITCH + cl * 16),
                 gkv[t] + (kvbase + k0 + rr) * Dk + cl * 8);
        }
        CP_COMMIT();
    };

    float o[8][4];
    #pragma unroll
    for (int nt = 0; nt < 8; nt++)
        #pragma unroll
        for (int j = 0; j < 4; j++) o[nt][j] = 0.f;
    float m0 = -1e30f, m1 = -1e30f, l0 = 0.f, l1 = 0.f;

    issue_kv(0, 0);
    issue_kv(1, 1);

    for (int it = 0; it < NT; it++) {
        if (it + 1 < NT) { CP_WAIT(1); } else { CP_WAIT(0); }
        __syncthreads();
        if (it + 2 < NT) issue_kv((it + 2) % AT_NSTAGE, it + 2);  // single-sync pipeline

        const uint32_t sb  = sbase + (it % AT_NSTAGE) * AT_STAGE;
        const uint32_t sKh = sb;
        const uint32_t sVh = sb + AT_TILE;
        const int k0 = it * 64;

        // ---- S = Q K^T (Q pre-scaled; paired x4 K loads) -----------------------
        float s[8][4];
        #pragma unroll
        for (int nt = 0; nt < 8; nt++)
            #pragma unroll
            for (int j = 0; j < 4; j++) s[nt][j] = 0.f;

        #pragma unroll
        for (int c = 0; c < 4; c++) {
            #pragma unroll
            for (int pr = 0; pr < 4; pr++) {
                uint32_t tmp[4];
                const int brow = pr * 16 + ((lane >> 4) & 1) * 8 + (lane & 7);
                const uint32_t boff =
                    (uint32_t)(brow * ATPITCH + (c * 2 + ((lane >> 3) & 1)) * 16);
                ldsm_x4(sKh + boff, tmp);
                mma_f16(s[2 * pr],     qh[c], tmp);
                mma_f16(s[2 * pr + 1], qh[c], tmp + 2);
            }
        }

        // ---- online softmax (exp2 domain, raw EX2) -----------------------------
        const bool need_mask = (k0 + 63 > q0);
        float t0 = -1e30f, t1 = -1e30f;
        #pragma unroll
        for (int nt = 0; nt < 8; nt++) {
            #pragma unroll
            for (int j = 0; j < 4; j++) {
                float t = s[nt][j];
                if (need_mask) {
                    const int col = k0 + nt * 8 + dc + (j & 1);
                    const int row = (j < 2) ? r : r + 8;
                    if (col > row) t = -1e30f;
                }
                s[nt][j] = t;
                if (j < 2) t0 = fmaxf(t0, t); else t1 = fmaxf(t1, t);
            }
        }
        t0 = fmaxf(t0, __shfl_xor_sync(0xffffffffu, t0, 1));
        t0 = fmaxf(t0, __shfl_xor_sync(0xffffffffu, t0, 2));
        t1 = fmaxf(t1, __shfl_xor_sync(0xffffffffu, t1, 1));
        t1 = fmaxf(t1, __shfl_xor_sync(0xffffffffu, t1, 2));
        const float om0 = m0, om1 = m1;
        m0 = fmaxf(m0, t0);
        m1 = fmaxf(m1, t1);

        float corr0 = 1.f, corr1 = 1.f;
        const bool chg = (m0 > om0) | (m1 > om1);
        if (__any_sync(0xffffffffu, chg)) {
            corr0 = ex2f(om0 - m0);          // exactly 1 when unchanged lanes? no:
            corr1 = ex2f(om1 - m1);          // per-lane corr; EX2(0)=1 exact
            #pragma unroll
            for (int nt = 0; nt < 8; nt++) {
                o[nt][0] *= corr0; o[nt][1] *= corr0;
                o[nt][2] *= corr1; o[nt][3] *= corr1;
            }
        }

        float ps0 = 0.f, ps1 = 0.f;
        #pragma unroll
        for (int nt = 0; nt < 8; nt++) {
            s[nt][0] = ex2f(s[nt][0] - m0);
            s[nt][1] = ex2f(s[nt][1] - m0);
            s[nt][2] = ex2f(s[nt][2] - m1);
            s[nt][3] = ex2f(s[nt][3] - m1);
            ps0 += s[nt][0] + s[nt][1];
            ps1 += s[nt][2] + s[nt][3];
        }
        ps0 += __shfl_xor_sync(0xffffffffu, ps0, 1);
        ps0 += __shfl_xor_sync(0xffffffffu, ps0, 2);
        ps1 += __shfl_xor_sync(0xffffffffu, ps1, 1);
        ps1 += __shfl_xor_sync(0xffffffffu, ps1, 2);
        l0 = l0 * corr0 + ps0;
        l1 = l1 * corr1 + ps1;

        // ---- O += P V (paired x4 trans V loads) --------------------------------
        #pragma unroll
        for (int u = 0; u < 4; u++) {
            uint32_t aph[4];
            aph[0] = pack_hf2(s[2*u][0],   s[2*u][1]);
            aph[1] = pack_hf2(s[2*u][2],   s[2*u][3]);
            aph[2] = pack_hf2(s[2*u+1][0], s[2*u+1][1]);
            aph[3] = pack_hf2(s[2*u+1][2], s[2*u+1][3]);
            #pragma unroll
            for (int pr = 0; pr < 4; pr++) {
                uint32_t tmp[4];
                const uint32_t voff =
                    (uint32_t)((u * 16 + (lane & 15)) * ATPITCH +
                               (2 * pr + ((lane >> 4) & 1)) * 16);
                ldsm_x4t(sVh + voff, tmp);
                mma_f16(o[2 * pr],     aph, tmp);
                mma_f16(o[2 * pr + 1], aph, tmp + 2);
            }
        }
    }

    // ---- epilogue: normalize, fp16 hi store, write [B,S,D] -------------------
    const float inv0 = 1.0f / l0, inv1 = 1.0f / l1;
    const int b = bh >> 4, h = bh & 15;
    const size_t base0 = ((size_t)b * Sq + r) * Dm + h * Dk;
    const size_t base1 = ((size_t)b * Sq + r + 8) * Dm + h * Dk;
    #pragma unroll
    for (int nt = 0; nt < 8; nt++) {
        const int col = nt * 8 + dc;
        *reinterpret_cast<uint32_t*>(Ohi + base0 + col) =
            pack_hf2(o[nt][0] * inv0, o[nt][1] * inv0);
        *reinterpret_cast<uint32_t*>(Ohi + base1 + col) =
            pack_hf2(o[nt][2] * inv1, o[nt][3] * inv1);
    }
}

// ---------------- launch -----------------------------------------------------
extern "C" void kernel_launch(void* const* d_in, const int* in_sizes, int n_in,
                              void* d_out, int out_size)
{
    const float* x   = (const float*)d_in[0];
    const float* Wq  = (const float*)d_in[1];
    const float* Wk  = (const float*)d_in[2];
    const float* Wv  = (const float*)d_in[3];
    const float* Wo  = (const float*)d_in[4];
    const int*   pos = (const int*)d_in[5];
    float* out = (float*)d_out;

    __half *xhi, *wqhi, *wkhi, *wvhi, *wohi;
    __half *qhi, *khi, *vhi, *ohi;
    float2* ropeTab;
    cudaGetSymbolAddress((void**)&xhi,  g_xhi);
    cudaGetSymbolAddress((void**)&wqhi, g_wqhi);
    cudaGetSymbolAddress((void**)&wkhi, g_wkhi);
    cudaGetSymbolAddress((void**)&wvhi, g_wvhi);
    cudaGetSymbolAddress((void**)&wohi, g_wohi);
    cudaGetSymbolAddress((void**)&qhi,  g_Qhi);
    cudaGetSymbolAddress((void**)&khi,  g_Khi);
    cudaGetSymbolAddress((void**)&vhi,  g_Vhi);
    cudaGetSymbolAddress((void**)&ohi,  g_Ohi);
    cudaGetSymbolAddress((void**)&ropeTab, g_rope);

    cudaFuncSetAttribute(qkv_gemm_kernel,
                         cudaFuncAttributeMaxDynamicSharedMemorySize, GEMM_SMEM);
    cudaFuncSetAttribute(wo_gemm_kernel,
                         cudaFuncAttributeMaxDynamicSharedMemorySize, GEMM_SMEM);
    cudaFuncSetAttribute(attn_mma_kernel,
                         cudaFuncAttributeMaxDynamicSharedMemorySize, ATT_SMEM);

    // 1) fused split pass (fp16 conversion, MLP=4) + RoPE cos/sin table
    split_all_kernel<<<SPLIT_CTAS + ROPE_CTAS, 256>>>(x, Wq, Wk, Wv, Wo, pos,
                                                      xhi, wqhi, wkhi, wvhi, wohi,
                                                      ropeTab);

    // 2) fused QKV projection (+RoPE, Q pre-scaled), single-term
    dim3 qkvgrid(3 * (Dm / BN), Mrows / BM);   // (24, 32)
    qkv_gemm_kernel<<<qkvgrid, 256, GEMM_SMEM>>>(xhi, wqhi, wkhi, wvhi,
                                                 qhi, khi, vhi, ropeTab);

    // 3) causal flash attention
    dim3 agrid(Sq / 128, Bsz * Hn);            // (16, 32)
    attn_mma_kernel<<<agrid, 256, ATT_SMEM>>>(qhi, khi, vhi, ohi);

    // 4) output projection (single-term)
    dim3 wogrid(Dm / BN, Mrows / BM);          // (8, 32)
    wo_gemm_kernel<<<wogrid, 256, GEMM_SMEM>>>(ohi, wohi, out);
}